// round 5
// baseline (speedup 1.0000x reference)
#include <cuda_runtime.h>
#include <cstdint>

#define NE     1024
#define DDIM   64
#define HW     4096
#define NPIX   131072
#define QELEMS (NPIX * DDIM)
#define TILE   128
#define NTILES 8
#define CAP    (8 * 1024 * 1024)

// ---------------- device scratch ----------------
__device__ unsigned g_qe[NE * 16];          // int8 codes, 16 u32/code
__device__ float2   g_seh[NE];              // (se, hn)
__device__ float    g_codeT[NE * DDIM];     // fp32 codebook [code][dim]
__device__ float    g_hn[NE];
__device__ unsigned g_neB, g_ndeB;          // float-bits of max ||e||, max ||delta_e||
__device__ unsigned g_qf[NPIX * 16];        // int8 pixels
__device__ float    g_fc[(size_t)NPIX * DDIM]; // contiguous fp32 pixel vectors
__device__ float    g_sf[NPIX];
__device__ float2   g_pn[NPIX];             // (||delta_f||, ||sf*qf||)
__device__ int      g_cnt, g_cnt2;
__device__ unsigned g_listP[CAP];
__device__ float    g_listV[CAP];
__device__ unsigned g_list2[CAP];
__device__ float    g_T[NPIX];
__device__ unsigned long long g_win[NPIX];
__device__ float    g_partial[512];

// ---------------- helpers ----------------
__device__ __forceinline__ unsigned smem_u32(const void* p) {
    unsigned a;
    asm("{ .reg .u64 t; cvta.to.shared.u64 t, %1; cvt.u32.u64 %0, t; }" : "=r"(a) : "l"(p));
    return a;
}
__device__ __forceinline__ void cpasync16(unsigned s, const void* g) {
    asm volatile("cp.async.cg.shared.global [%0], [%1], 16;" :: "r"(s), "l"(g));
}
__device__ __forceinline__ void cpasync8(unsigned s, const void* g) {
    asm volatile("cp.async.ca.shared.global [%0], [%1], 8;" :: "r"(s), "l"(g));
}
__device__ __forceinline__ void cpacommit() { asm volatile("cp.async.commit_group;"); }
template <int N> __device__ __forceinline__ void cpawait() {
    asm volatile("cp.async.wait_group %0;" :: "n"(N));
}
__device__ __forceinline__ unsigned sortable(float s) {
    unsigned u = __float_as_uint(s);
    return (u & 0x80000000u) ? ~u : (u | 0x80000000u);
}
__device__ __forceinline__ int q8(float v, float inv) {
    int q = (int)rintf(v * inv);
    return q < -127 ? -127 : (q > 127 ? 127 : q);
}
__device__ __forceinline__ unsigned pack4(int a, int b, int c, int d) {
    return (unsigned)(a & 0xFF) | ((unsigned)(b & 0xFF) << 8)
         | ((unsigned)(c & 0xFF) << 16) | ((unsigned)(d & 0xFF) << 24);
}

// ---------------------------------------------------------------------------
__global__ void initk() {
    g_cnt = 0; g_cnt2 = 0; g_neB = 0; g_ndeB = 0;
}

// ---------------------------------------------------------------------------
// packB: embed [DDIM, NE] -> int8 codes + scales + norms + fp32 codebook
// ---------------------------------------------------------------------------
__global__ void packB(const float* __restrict__ embed) {
    int j = blockIdx.x * 256 + threadIdx.x;
    if (j >= NE) return;
    float e[DDIM];
    float m = 0.f, n2 = 0.f;
#pragma unroll
    for (int d = 0; d < DDIM; d++) {
        float v = embed[d * NE + j];
        e[d] = v;
        g_codeT[j * DDIM + d] = v;
        m = fmaxf(m, fabsf(v));
        n2 += v * v;
    }
    float hn = 0.5f * n2;
    g_hn[j] = hn;
    float se = (m > 0.f) ? m * (1.0f / 127.0f) : 1.0f;
    float inv = 1.0f / se;
    float d2 = 0.f;
    int q[DDIM];
#pragma unroll
    for (int d = 0; d < DDIM; d++) {
        q[d] = q8(e[d], inv);
        float r = e[d] - se * (float)q[d];
        d2 += r * r;
    }
#pragma unroll
    for (int k = 0; k < 16; k++)
        g_qe[j * 16 + k] = pack4(q[4 * k], q[4 * k + 1], q[4 * k + 2], q[4 * k + 3]);
    g_seh[j] = make_float2(se, hn);
    atomicMax(&g_neB, __float_as_uint(sqrtf(n2)));
    atomicMax(&g_ndeB, __float_as_uint(sqrtf(d2)));
}

// ---------------------------------------------------------------------------
// packX: x [B,D,H,W] -> per-pixel int8 + scale + norms + contiguous fp32 copy
// ---------------------------------------------------------------------------
__global__ void __launch_bounds__(128) packX(const float* __restrict__ x) {
    const int p = blockIdx.x * 128 + threadIdx.x;
    const int b = p >> 12, hw = p & 4095;
    const float* xb = x + (size_t)b * DDIM * HW + hw;
    float f[DDIM];
    float m = 0.f;
#pragma unroll
    for (int d = 0; d < DDIM; d++) {
        f[d] = xb[d * HW];             // coalesced across threads
        m = fmaxf(m, fabsf(f[d]));
    }
    float sf = (m > 0.f) ? m * (1.0f / 127.0f) : 1.0f;
    float inv = 1.0f / sf;
    float d2 = 0.f, n2 = 0.f;
    int q[DDIM];
#pragma unroll
    for (int d = 0; d < DDIM; d++) {
        q[d] = q8(f[d], inv);
        float fh = sf * (float)q[d];
        float r = f[d] - fh;
        d2 += r * r;
        n2 += fh * fh;
    }
    unsigned* qd = g_qf + (size_t)p * 16;
#pragma unroll
    for (int k = 0; k < 4; k++) {
        uint4 u = make_uint4(pack4(q[16 * k], q[16 * k + 1], q[16 * k + 2], q[16 * k + 3]),
                             pack4(q[16 * k + 4], q[16 * k + 5], q[16 * k + 6], q[16 * k + 7]),
                             pack4(q[16 * k + 8], q[16 * k + 9], q[16 * k + 10], q[16 * k + 11]),
                             pack4(q[16 * k + 12], q[16 * k + 13], q[16 * k + 14], q[16 * k + 15]));
        ((uint4*)qd)[k] = u;
    }
    float4* fc = (float4*)(g_fc + (size_t)p * DDIM);
#pragma unroll
    for (int k = 0; k < 16; k++)
        fc[k] = make_float4(f[4 * k], f[4 * k + 1], f[4 * k + 2], f[4 * k + 3]);
    g_sf[p] = sf;
    g_pn[p] = make_float2(sqrtf(d2), sqrtf(n2));
}

// ---------------------------------------------------------------------------
// vq_pass: dp4a scores for all 1024 codes per pixel; running-threshold emit.
// 1 pixel/thread, 128 threads/CTA, grid 1024.
// ---------------------------------------------------------------------------
__global__ void __launch_bounds__(128, 6) vq_pass() {
    __shared__ unsigned sQ[2][TILE * 16];   // 2 x 8 KB
    __shared__ float2   sS[2][TILE];        // 2 x 1 KB

    const int t = threadIdx.x, lane = t & 31;
    const int p = blockIdx.x * 128 + t;

    // per-pixel quantized vector
    unsigned F[16];
    const unsigned* qf = g_qf + (size_t)p * 16;
#pragma unroll
    for (int k = 0; k < 16; k++) F[k] = qf[k];
    const float sf = g_sf[p];
    const float2 pn = g_pn[p];
    const float nem = __uint_as_float(g_neB);
    const float ndem = __uint_as_float(g_ndeB);
    const float w2 = 2.0f * (1.02f * (pn.x * nem + pn.y * ndem) + 1e-3f);

    // prefetch tile 0
    {
        unsigned sq = smem_u32(&sQ[0][0]) + t * 64;
        const char* src = (const char*)(g_qe + t * 16);
#pragma unroll
        for (int k = 0; k < 4; k++) cpasync16(sq + k * 16, src + k * 16);
        cpasync8(smem_u32(&sS[0][0]) + t * 8, &g_seh[t]);
        cpacommit();
    }

    float m = -1e30f;

#pragma unroll 1
    for (int tile = 0; tile < NTILES; tile++) {
        if (tile + 1 < NTILES) {
            int nb = (tile + 1) & 1;
            unsigned sq = smem_u32(&sQ[nb][0]) + t * 64;
            const char* src = (const char*)(g_qe + ((tile + 1) * TILE + t) * 16);
#pragma unroll
            for (int k = 0; k < 4; k++) cpasync16(sq + k * 16, src + k * 16);
            cpasync8(smem_u32(&sS[nb][0]) + t * 8, &g_seh[(tile + 1) * TILE + t]);
            cpacommit();
            cpawait<1>();
        } else {
            cpawait<0>();
        }
        __syncthreads();

        const int buf = tile & 1;
        const int jb = tile * TILE;
#pragma unroll 2
        for (int c = 0; c < TILE; c++) {
            const int4* qq = (const int4*)&sQ[buf][c * 16];
            int a0 = 0, a1 = 0, a2 = 0, a3 = 0;
#pragma unroll
            for (int k = 0; k < 4; k++) {
                int4 u = qq[k];
                a0 = __dp4a(u.x, (int)F[4 * k + 0], a0);
                a1 = __dp4a(u.y, (int)F[4 * k + 1], a1);
                a2 = __dp4a(u.z, (int)F[4 * k + 2], a2);
                a3 = __dp4a(u.w, (int)F[4 * k + 3], a3);
            }
            int acc = (a0 + a1) + (a2 + a3);
            float2 sh = sS[buf][c];
            float v = fmaf((float)acc, sf * sh.x, -sh.y);
            bool fl = v >= m - w2;
            m = fmaxf(m, v);
            unsigned msk = __ballot_sync(0xFFFFFFFFu, fl);
            if (msk) {
                int ldr = __ffs(msk) - 1;
                int base;
                if (lane == ldr) base = atomicAdd(&g_cnt, __popc(msk));
                base = __shfl_sync(0xFFFFFFFFu, base, ldr);
                if (fl) {
                    int o = base + __popc(msk & ((1u << lane) - 1));
                    if (o < CAP) {
                        g_listP[o] = ((unsigned)p << 10) | (unsigned)(jb + c);
                        g_listV[o] = v;
                    }
                }
            }
        }
        __syncthreads();
    }

    g_T[p] = m - w2;
    g_win[p] = 0ULL;
}

// ---------------------------------------------------------------------------
// filter: keep only entries with v >= final per-pixel threshold
// ---------------------------------------------------------------------------
__global__ void filter() {
    int cnt = g_cnt; if (cnt > CAP) cnt = CAP;
    const int lane = threadIdx.x & 31;
    for (int i = blockIdx.x * blockDim.x + threadIdx.x; ; i += gridDim.x * blockDim.x) {
        bool active = i < cnt;
        unsigned e = 0; bool keep = false;
        if (active) {
            e = g_listP[i];
            keep = g_listV[i] >= g_T[e >> 10];
        }
        unsigned msk = __ballot_sync(0xFFFFFFFFu, keep);
        if (msk) {
            int ldr = __ffs(msk) - 1;
            int base;
            if (lane == ldr) base = atomicAdd(&g_cnt2, __popc(msk));
            base = __shfl_sync(0xFFFFFFFFu, base, ldr);
            if (keep) g_list2[base + __popc(msk & ((1u << lane) - 1))] = e;
        }
        if (__all_sync(0xFFFFFFFFu, !active)) break;
    }
}

// ---------------------------------------------------------------------------
// rescore: exact fp32 scores for survivors; atomicMax packed (score, idx)
// ---------------------------------------------------------------------------
__global__ void rescore() {
    int cnt = g_cnt2; if (cnt > CAP) cnt = CAP;
    const int lane = threadIdx.x & 31;
    const int wg = (blockIdx.x * blockDim.x + threadIdx.x) >> 5;
    const int nw = (gridDim.x * blockDim.x) >> 5;
    for (int i = wg; i < cnt; i += nw) {
        unsigned e = g_list2[i];
        unsigned p = e >> 10;
        unsigned j = e & 1023u;
        float2 fv = ((const float2*)(g_fc + (size_t)p * DDIM))[lane];
        float2 cv = ((const float2*)(g_codeT + (size_t)j * DDIM))[lane];
        float s = fv.x * cv.x + fv.y * cv.y;
#pragma unroll
        for (int o = 16; o; o >>= 1) s += __shfl_xor_sync(0xFFFFFFFFu, s, o);
        if (lane == 0) {
            s -= g_hn[j];
            unsigned long long key =
                ((unsigned long long)sortable(s) << 32) | (unsigned)(1023u - j);
            atomicMax(&g_win[p], key);
        }
    }
}

// ---------------------------------------------------------------------------
// final_gather: write quantized output + loss partials
// ---------------------------------------------------------------------------
__global__ void __launch_bounds__(256) final_gather(const float* __restrict__ x,
                                                    float* __restrict__ out) {
    __shared__ float sRed[8];
    const int t = threadIdx.x;
    const int p = blockIdx.x * 256 + t;
    const int b = p >> 12, hw = p & 4095;
    const int idx = 1023 - (int)(g_win[p] & 0xFFFFFFFFull);

    const float* xb = x + (size_t)b * DDIM * HW + hw;
    float* ob = out + (size_t)b * DDIM * HW + hw;
    const float4* cr = (const float4*)(g_codeT + (size_t)idx * DDIM);
    float loss = 0.f;
#pragma unroll
    for (int kk = 0; kk < 16; kk++) {
        float4 q = cr[kk];
        int d = 4 * kk;
        float r;
        ob[(d + 0) * HW] = q.x; r = q.x - xb[(d + 0) * HW]; loss += r * r;
        ob[(d + 1) * HW] = q.y; r = q.y - xb[(d + 1) * HW]; loss += r * r;
        ob[(d + 2) * HW] = q.z; r = q.z - xb[(d + 2) * HW]; loss += r * r;
        ob[(d + 3) * HW] = q.w; r = q.w - xb[(d + 3) * HW]; loss += r * r;
    }
#pragma unroll
    for (int o = 16; o; o >>= 1) loss += __shfl_xor_sync(0xFFFFFFFFu, loss, o);
    if ((t & 31) == 0) sRed[t >> 5] = loss;
    __syncthreads();
    if (t == 0) {
        float s = 0.f;
#pragma unroll
        for (int w = 0; w < 8; w++) s += sRed[w];
        g_partial[blockIdx.x] = s;
    }
}

__global__ void fin_kernel(float* __restrict__ out, int last) {
    __shared__ float sRed[16];
    int t = threadIdx.x;  // 512
    float v = g_partial[t];
#pragma unroll
    for (int o = 16; o; o >>= 1) v += __shfl_xor_sync(0xFFFFFFFFu, v, o);
    if ((t & 31) == 0) sRed[t >> 5] = v;
    __syncthreads();
    if (t == 0) {
        double s = 0.0;
#pragma unroll
        for (int w = 0; w < 16; w++) s += (double)sRed[w];
        out[last] = (float)(s / (double)QELEMS);
    }
}

// ---------------------------------------------------------------------------
extern "C" void kernel_launch(void* const* d_in, const int* in_sizes, int n_in,
                              void* d_out, int out_size) {
    const float* x = (const float*)d_in[0];
    const float* embed = (const float*)d_in[1];
    if (n_in >= 2 && in_sizes[0] == NE * DDIM && in_sizes[1] == QELEMS) {
        const float* tmp = x; x = embed; embed = tmp;
    }
    float* out = (float*)d_out;

    initk<<<1, 1>>>();
    packB<<<4, 256>>>(embed);
    packX<<<NPIX / 128, 128>>>(x);
    vq_pass<<<NPIX / 128, 128>>>();
    filter<<<256, 256>>>();
    rescore<<<1024, 256>>>();
    final_gather<<<NPIX / 256, 256>>>(x, out);
    fin_kernel<<<1, 512>>>(out, out_size - 1);
}

// round 6
// speedup vs baseline: 1.6879x; 1.6879x over previous
#include <cuda_runtime.h>
#include <cstdint>

#define NE     1024
#define DDIM   64
#define HW     4096
#define NPIX   131072
#define QELEMS (NPIX * DDIM)
#define TILE   128
#define NTILES 8
#define SLAB   32

// ---------------- device scratch ----------------
__device__ unsigned g_qe[NE * 16];            // int8 codes, 16 u32/code
__device__ float2   g_seh[NE];                // (se, hn)
__device__ float    g_codeT[NE * DDIM];       // fp32 codebook [code][dim]
__device__ float    g_hn[NE];
__device__ unsigned g_neB, g_ndeB;            // bits of max ||e||, max ||delta_e||
__device__ float    g_fc[(size_t)NPIX * DDIM];     // contiguous fp32 pixel vectors
__device__ float2   g_slab[(size_t)NPIX * SLAB];   // per-pixel candidates (v, j)
__device__ int      g_cntP[NPIX];
__device__ float    g_T[NPIX];
__device__ int      g_widx[NPIX];
__device__ float    g_partial[512];

// ---------------- helpers ----------------
__device__ __forceinline__ unsigned smem_u32(const void* p) {
    unsigned a;
    asm("{ .reg .u64 t; cvta.to.shared.u64 t, %1; cvt.u32.u64 %0, t; }" : "=r"(a) : "l"(p));
    return a;
}
__device__ __forceinline__ void cpasync16(unsigned s, const void* g) {
    asm volatile("cp.async.cg.shared.global [%0], [%1], 16;" :: "r"(s), "l"(g));
}
__device__ __forceinline__ void cpasync8(unsigned s, const void* g) {
    asm volatile("cp.async.ca.shared.global [%0], [%1], 8;" :: "r"(s), "l"(g));
}
__device__ __forceinline__ void cpacommit() { asm volatile("cp.async.commit_group;"); }
template <int N> __device__ __forceinline__ void cpawait() {
    asm volatile("cp.async.wait_group %0;" :: "n"(N));
}
__device__ __forceinline__ int q8(float v, float inv) {
    int q = (int)rintf(v * inv);
    return q < -127 ? -127 : (q > 127 ? 127 : q);
}
__device__ __forceinline__ unsigned pack4(int a, int b, int c, int d) {
    return (unsigned)(a & 0xFF) | ((unsigned)(b & 0xFF) << 8)
         | ((unsigned)(c & 0xFF) << 16) | ((unsigned)(d & 0xFF) << 24);
}

// ---------------------------------------------------------------------------
// packB: embed [DDIM, NE] -> int8 codes + (se,hn) + fp32 codebook + norm maxima
// ---------------------------------------------------------------------------
__global__ void packB(const float* __restrict__ embed) {
    int j = blockIdx.x * 256 + threadIdx.x;
    if (j >= NE) return;
    float e[DDIM];
    float m = 0.f, n2 = 0.f;
#pragma unroll
    for (int d = 0; d < DDIM; d++) {
        float v = embed[d * NE + j];
        e[d] = v;
        g_codeT[j * DDIM + d] = v;
        m = fmaxf(m, fabsf(v));
        n2 += v * v;
    }
    float hn = 0.5f * n2;
    g_hn[j] = hn;
    float se = (m > 0.f) ? m * (1.0f / 127.0f) : 1.0f;
    float inv = 1.0f / se;
    float d2 = 0.f;
    int q[DDIM];
#pragma unroll
    for (int d = 0; d < DDIM; d++) {
        q[d] = q8(e[d], inv);
        float r = e[d] - se * (float)q[d];
        d2 += r * r;
    }
#pragma unroll
    for (int k = 0; k < 16; k++)
        g_qe[j * 16 + k] = pack4(q[4 * k], q[4 * k + 1], q[4 * k + 2], q[4 * k + 3]);
    g_seh[j] = make_float2(se, hn);
    atomicMax(&g_neB, __float_as_uint(sqrtf(n2)));
    atomicMax(&g_ndeB, __float_as_uint(sqrtf(d2)));
}

// ---------------------------------------------------------------------------
// prep_pixel: load strided x vector, quantize, write contiguous fp32 copy,
// return packed int8 words + scale + certificate width
// ---------------------------------------------------------------------------
__device__ __forceinline__ void prep_pixel(const float* __restrict__ xp, int p,
                                           unsigned* F, float& sf, float& w2,
                                           float nem, float ndem) {
    float f[DDIM];
    float m = 0.f;
#pragma unroll
    for (int d = 0; d < DDIM; d++) {
        f[d] = xp[d * HW];
        m = fmaxf(m, fabsf(f[d]));
    }
    sf = (m > 0.f) ? m * (1.0f / 127.0f) : 1.0f;
    float inv = 1.0f / sf;
    float d2 = 0.f, n2 = 0.f;
    float4* fc = (float4*)(g_fc + (size_t)p * DDIM);
#pragma unroll
    for (int k = 0; k < 16; k++) {
        float f0 = f[4 * k], f1 = f[4 * k + 1], f2 = f[4 * k + 2], f3 = f[4 * k + 3];
        int q0 = q8(f0, inv), q1 = q8(f1, inv), q2 = q8(f2, inv), q3 = q8(f3, inv);
        F[k] = pack4(q0, q1, q2, q3);
        float h0 = sf * (float)q0, h1 = sf * (float)q1, h2 = sf * (float)q2, h3 = sf * (float)q3;
        float r0 = f0 - h0, r1 = f1 - h1, r2 = f2 - h2, r3 = f3 - h3;
        d2 += r0 * r0 + r1 * r1 + r2 * r2 + r3 * r3;
        n2 += h0 * h0 + h1 * h1 + h2 * h2 + h3 * h3;
        fc[k] = make_float4(f0, f1, f2, f3);
    }
    w2 = 2.0f * (1.02f * (sqrtf(d2) * nem + sqrtf(n2) * ndem) + 1e-3f);
}

// ---------------------------------------------------------------------------
// vq_pass: dp4a over all 1024 codes, 2 pixels/thread, private-slab emission
// ---------------------------------------------------------------------------
__global__ void __launch_bounds__(64, 8) vq_pass(const float* __restrict__ x) {
    __shared__ unsigned sQ[2][TILE * 16];   // 2 x 8 KB
    __shared__ float2   sS[2][TILE];        // 2 x 1 KB

    const int t = threadIdx.x;
    const int p0 = blockIdx.x * 128 + t;
    const int p1 = p0 + 64;
    const int b = p0 >> 12;
    const float* xbase = x + (size_t)b * DDIM * HW;

    // prefetch tile 0
    {
        unsigned sq = smem_u32(&sQ[0][0]);
        unsigned ss = smem_u32(&sS[0][0]);
#pragma unroll
        for (int r = t; r < TILE; r += 64) {
            const char* src = (const char*)(g_qe + r * 16);
#pragma unroll
            for (int k = 0; k < 4; k++) cpasync16(sq + r * 64 + k * 16, src + k * 16);
            cpasync8(ss + r * 8, &g_seh[r]);
        }
        cpacommit();
    }

    const float nem = __uint_as_float(g_neB);
    const float ndem = __uint_as_float(g_ndeB);

    unsigned FA[16], FB[16];
    float sfA, w2A, sfB, w2B;
    prep_pixel(xbase + (p0 & 4095), p0, FA, sfA, w2A, nem, ndem);
    prep_pixel(xbase + (p1 & 4095), p1, FB, sfB, w2B, nem, ndem);

    float mA = -1e30f, mB = -1e30f;
    float tA = -1e30f, tB = -1e30f;
    int cA = 0, cB = 0;
    float2* slabA = g_slab + (size_t)p0 * SLAB;
    float2* slabB = g_slab + (size_t)p1 * SLAB;

#pragma unroll 1
    for (int tile = 0; tile < NTILES; tile++) {
        if (tile + 1 < NTILES) {
            int nb = (tile + 1) & 1;
            unsigned sq = smem_u32(&sQ[nb][0]);
            unsigned ss = smem_u32(&sS[nb][0]);
#pragma unroll
            for (int r = t; r < TILE; r += 64) {
                const char* src = (const char*)(g_qe + ((tile + 1) * TILE + r) * 16);
#pragma unroll
                for (int k = 0; k < 4; k++) cpasync16(sq + r * 64 + k * 16, src + k * 16);
                cpasync8(ss + r * 8, &g_seh[(tile + 1) * TILE + r]);
            }
            cpacommit();
            cpawait<1>();
        } else {
            cpawait<0>();
        }
        __syncthreads();

        const int buf = tile & 1;
        const int jb = tile * TILE;
#pragma unroll 2
        for (int c = 0; c < TILE; c++) {
            const int4* qq = (const int4*)&sQ[buf][c * 16];
            float2 sh = sS[buf][c];
            int a0 = 0, a1 = 0, a2 = 0, a3 = 0;
            int e0 = 0, e1 = 0, e2 = 0, e3 = 0;
#pragma unroll
            for (int k = 0; k < 4; k++) {
                int4 u = qq[k];
                a0 = __dp4a(u.x, (int)FA[4 * k + 0], a0);
                a1 = __dp4a(u.y, (int)FA[4 * k + 1], a1);
                a2 = __dp4a(u.z, (int)FA[4 * k + 2], a2);
                a3 = __dp4a(u.w, (int)FA[4 * k + 3], a3);
                e0 = __dp4a(u.x, (int)FB[4 * k + 0], e0);
                e1 = __dp4a(u.y, (int)FB[4 * k + 1], e1);
                e2 = __dp4a(u.z, (int)FB[4 * k + 2], e2);
                e3 = __dp4a(u.w, (int)FB[4 * k + 3], e3);
            }
            int accA = (a0 + a1) + (a2 + a3);
            int accB = (e0 + e1) + (e2 + e3);
            float vA = fmaf((float)accA, sfA * sh.x, -sh.y);
            float vB = fmaf((float)accB, sfB * sh.x, -sh.y);
            if (vA >= tA) {
                if (cA < SLAB) slabA[cA] = make_float2(vA, __int_as_float(jb + c));
                cA++;
                if (vA > mA) { mA = vA; tA = mA - w2A; }
            }
            if (vB >= tB) {
                if (cB < SLAB) slabB[cB] = make_float2(vB, __int_as_float(jb + c));
                cB++;
                if (vB > mB) { mB = vB; tB = mB - w2B; }
            }
        }
        __syncthreads();
    }

    g_T[p0] = mA - w2A;
    g_T[p1] = mB - w2B;
    g_cntP[p0] = cA;
    g_cntP[p1] = cB;
}

// ---------------------------------------------------------------------------
// resolve: warp per pixel. Exact fp32 rescore of surviving candidates
// (or full scan on slab overflow). Lowest-index tie-break.
// ---------------------------------------------------------------------------
__global__ void __launch_bounds__(256) resolve() {
    const int lane = threadIdx.x & 31;
    const int p = (blockIdx.x * blockDim.x + threadIdx.x) >> 5;

    const int cnt = g_cntP[p];
    const float T = g_T[p];
    const float2 fv = ((const float2*)(g_fc + (size_t)p * DDIM))[lane];

    float bests = -3e38f;
    int bestj = 0;

    if (cnt <= SLAB) {
        float2 ent = (lane < cnt) ? g_slab[(size_t)p * SLAB + lane]
                                  : make_float2(-3e38f, 0.f);
        unsigned mask = __ballot_sync(0xFFFFFFFFu, ent.x >= T);
        while (mask) {
            int src = __ffs(mask) - 1;
            mask &= mask - 1;
            int j = __shfl_sync(0xFFFFFFFFu, __float_as_int(ent.y), src);
            float2 cv = ((const float2*)(g_codeT + (size_t)j * DDIM))[lane];
            float s = fmaf(fv.x, cv.x, fv.y * cv.y);
#pragma unroll
            for (int o = 16; o; o >>= 1) s += __shfl_xor_sync(0xFFFFFFFFu, s, o);
            s -= g_hn[j];
            if (s > bests) { bests = s; bestj = j; }   // increasing j -> lowest idx on tie
        }
    } else {
        // rare overflow: exact scan of all codes
        for (int j = 0; j < NE; j++) {
            float2 cv = ((const float2*)(g_codeT + (size_t)j * DDIM))[lane];
            float s = fmaf(fv.x, cv.x, fv.y * cv.y);
#pragma unroll
            for (int o = 16; o; o >>= 1) s += __shfl_xor_sync(0xFFFFFFFFu, s, o);
            s -= g_hn[j];
            if (s > bests) { bests = s; bestj = j; }
        }
    }
    if (lane == 0) g_widx[p] = bestj;
}

// ---------------------------------------------------------------------------
// final_gather: write quantized output + loss partials
// ---------------------------------------------------------------------------
__global__ void __launch_bounds__(256) final_gather(const float* __restrict__ x,
                                                    float* __restrict__ out) {
    __shared__ float sRed[8];
    const int t = threadIdx.x;
    const int p = blockIdx.x * 256 + t;
    const int b = p >> 12, hw = p & 4095;
    const int idx = g_widx[p];

    const float* xb = x + (size_t)b * DDIM * HW + hw;
    float* ob = out + (size_t)b * DDIM * HW + hw;
    const float4* cr = (const float4*)(g_codeT + (size_t)idx * DDIM);
    float loss = 0.f;
#pragma unroll
    for (int kk = 0; kk < 16; kk++) {
        float4 q = cr[kk];
        int d = 4 * kk;
        float r;
        ob[(d + 0) * HW] = q.x; r = q.x - xb[(d + 0) * HW]; loss += r * r;
        ob[(d + 1) * HW] = q.y; r = q.y - xb[(d + 1) * HW]; loss += r * r;
        ob[(d + 2) * HW] = q.z; r = q.z - xb[(d + 2) * HW]; loss += r * r;
        ob[(d + 3) * HW] = q.w; r = q.w - xb[(d + 3) * HW]; loss += r * r;
    }
#pragma unroll
    for (int o = 16; o; o >>= 1) loss += __shfl_xor_sync(0xFFFFFFFFu, loss, o);
    if ((t & 31) == 0) sRed[t >> 5] = loss;
    __syncthreads();
    if (t == 0) {
        float s = 0.f;
#pragma unroll
        for (int w = 0; w < 8; w++) s += sRed[w];
        g_partial[blockIdx.x] = s;
    }
}

__global__ void fin_kernel(float* __restrict__ out, int last) {
    __shared__ float sRed[16];
    int t = threadIdx.x;  // 512
    float v = g_partial[t];
#pragma unroll
    for (int o = 16; o; o >>= 1) v += __shfl_xor_sync(0xFFFFFFFFu, v, o);
    if ((t & 31) == 0) sRed[t >> 5] = v;
    __syncthreads();
    if (t == 0) {
        double s = 0.0;
#pragma unroll
        for (int w = 0; w < 16; w++) s += (double)sRed[w];
        out[last] = (float)(s / (double)QELEMS);
    }
}

// ---------------------------------------------------------------------------
extern "C" void kernel_launch(void* const* d_in, const int* in_sizes, int n_in,
                              void* d_out, int out_size) {
    const float* x = (const float*)d_in[0];
    const float* embed = (const float*)d_in[1];
    if (n_in >= 2 && in_sizes[0] == NE * DDIM && in_sizes[1] == QELEMS) {
        const float* tmp = x; x = embed; embed = tmp;
    }
    float* out = (float*)d_out;

    packB<<<4, 256>>>(embed);
    vq_pass<<<NPIX / 128, 64>>>(x);
    resolve<<<NPIX / 8, 256>>>();
    final_gather<<<NPIX / 256, 256>>>(x, out);
    fin_kernel<<<1, 512>>>(out, out_size - 1);
}

// round 7
// speedup vs baseline: 1.7061x; 1.0108x over previous
#include <cuda_runtime.h>
#include <cstdint>

#define NE     1024
#define DDIM   64
#define HW     4096
#define NPIX   131072
#define QELEMS (NPIX * DDIM)
#define TILE   128
#define NTILES 8
#define SLAB   32

// ---------------- device scratch ----------------
__device__ unsigned g_qe[NE * 16];            // int8 codes, 16 u32/code
__device__ float2   g_seh[NE];                // (se, hn)
__device__ float    g_codeT[NE * DDIM];       // fp32 codebook [code][dim]
__device__ float    g_hn[NE];
__device__ unsigned g_neB, g_ndeB;            // bits of max ||e||, max ||delta_e||
__device__ float    g_fc[(size_t)NPIX * DDIM];     // contiguous fp32 pixel vectors
__device__ float2   g_slab[(size_t)NPIX * SLAB];   // per-pixel candidates (v, j)
__device__ int      g_cntP[NPIX];
__device__ float    g_T[NPIX];
__device__ int      g_widx[NPIX];
__device__ float    g_partial[512];

// ---------------- helpers ----------------
__device__ __forceinline__ unsigned smem_u32(const void* p) {
    unsigned a;
    asm("{ .reg .u64 t; cvta.to.shared.u64 t, %1; cvt.u32.u64 %0, t; }" : "=r"(a) : "l"(p));
    return a;
}
__device__ __forceinline__ void cpasync16(unsigned s, const void* g) {
    asm volatile("cp.async.cg.shared.global [%0], [%1], 16;" :: "r"(s), "l"(g));
}
__device__ __forceinline__ void cpasync8(unsigned s, const void* g) {
    asm volatile("cp.async.ca.shared.global [%0], [%1], 8;" :: "r"(s), "l"(g));
}
__device__ __forceinline__ void cpacommit() { asm volatile("cp.async.commit_group;"); }
template <int N> __device__ __forceinline__ void cpawait() {
    asm volatile("cp.async.wait_group %0;" :: "n"(N));
}
__device__ __forceinline__ int q8(float v, float inv) {
    int q = (int)rintf(v * inv);
    return q < -127 ? -127 : (q > 127 ? 127 : q);
}
__device__ __forceinline__ unsigned pack4(int a, int b, int c, int d) {
    return (unsigned)(a & 0xFF) | ((unsigned)(b & 0xFF) << 8)
         | ((unsigned)(c & 0xFF) << 16) | ((unsigned)(d & 0xFF) << 24);
}

// Branchless candidate emission: predicated store + predicated count bump.
// No BSSY/BSYNC — keeps the scheduler free to pipeline surrounding LDS/dp4a.
__device__ __forceinline__ void emit(float v, float t, int& cnt,
                                     unsigned long long slab, unsigned jbits) {
    asm volatile(
        "{\n\t"
        ".reg .pred p;\n\t"
        ".reg .s32 ci;\n\t"
        ".reg .s64 ad;\n\t"
        "setp.ge.f32 p, %1, %2;\n\t"
        "min.s32 ci, %0, 31;\n\t"
        "mad.wide.s32 ad, ci, 8, %3;\n\t"
        "@p st.global.v2.b32 [ad], {%4, %5};\n\t"
        "@p add.s32 %0, %0, 1;\n\t"
        "}\n"
        : "+r"(cnt)
        : "f"(v), "f"(t), "l"((long long)slab), "r"(__float_as_uint(v)), "r"(jbits));
}

// ---------------------------------------------------------------------------
// packB: embed [DDIM, NE] -> int8 codes + (se,hn) + fp32 codebook + norm maxima
// ---------------------------------------------------------------------------
__global__ void packB(const float* __restrict__ embed) {
    int j = blockIdx.x * 256 + threadIdx.x;
    if (j >= NE) return;
    float e[DDIM];
    float m = 0.f, n2 = 0.f;
#pragma unroll
    for (int d = 0; d < DDIM; d++) {
        float v = embed[d * NE + j];
        e[d] = v;
        g_codeT[j * DDIM + d] = v;
        m = fmaxf(m, fabsf(v));
        n2 += v * v;
    }
    float hn = 0.5f * n2;
    g_hn[j] = hn;
    float se = (m > 0.f) ? m * (1.0f / 127.0f) : 1.0f;
    float inv = 1.0f / se;
    float d2 = 0.f;
    int q[DDIM];
#pragma unroll
    for (int d = 0; d < DDIM; d++) {
        q[d] = q8(e[d], inv);
        float r = e[d] - se * (float)q[d];
        d2 += r * r;
    }
#pragma unroll
    for (int k = 0; k < 16; k++)
        g_qe[j * 16 + k] = pack4(q[4 * k], q[4 * k + 1], q[4 * k + 2], q[4 * k + 3]);
    g_seh[j] = make_float2(se, hn);
    atomicMax(&g_neB, __float_as_uint(sqrtf(n2)));
    atomicMax(&g_ndeB, __float_as_uint(sqrtf(d2)));
}

// ---------------------------------------------------------------------------
// prep_pixel: load strided x vector, quantize, write contiguous fp32 copy
// ---------------------------------------------------------------------------
__device__ __forceinline__ void prep_pixel(const float* __restrict__ xp, int p,
                                           unsigned* F, float& sf, float& w2,
                                           float nem, float ndem) {
    float f[DDIM];
    float m = 0.f;
#pragma unroll
    for (int d = 0; d < DDIM; d++) {
        f[d] = xp[d * HW];
        m = fmaxf(m, fabsf(f[d]));
    }
    sf = (m > 0.f) ? m * (1.0f / 127.0f) : 1.0f;
    float inv = 1.0f / sf;
    float d2 = 0.f, n2 = 0.f;
    float4* fc = (float4*)(g_fc + (size_t)p * DDIM);
#pragma unroll
    for (int k = 0; k < 16; k++) {
        float f0 = f[4 * k], f1 = f[4 * k + 1], f2 = f[4 * k + 2], f3 = f[4 * k + 3];
        int q0 = q8(f0, inv), q1 = q8(f1, inv), q2 = q8(f2, inv), q3 = q8(f3, inv);
        F[k] = pack4(q0, q1, q2, q3);
        float h0 = sf * (float)q0, h1 = sf * (float)q1, h2 = sf * (float)q2, h3 = sf * (float)q3;
        float r0 = f0 - h0, r1 = f1 - h1, r2 = f2 - h2, r3 = f3 - h3;
        d2 += r0 * r0 + r1 * r1 + r2 * r2 + r3 * r3;
        n2 += h0 * h0 + h1 * h1 + h2 * h2 + h3 * h3;
        fc[k] = make_float4(f0, f1, f2, f3);
    }
    w2 = 2.0f * (1.02f * (sqrtf(d2) * nem + sqrtf(n2) * ndem) + 1e-3f);
}

// ---------------------------------------------------------------------------
// vq_pass: dp4a over all 1024 codes, 2 pixels/thread, branchless emission
// ---------------------------------------------------------------------------
__global__ void __launch_bounds__(64, 8) vq_pass(const float* __restrict__ x) {
    __shared__ unsigned sQ[2][TILE * 16];   // 2 x 8 KB
    __shared__ float2   sS[2][TILE];        // 2 x 1 KB

    const int t = threadIdx.x;
    const int p0 = blockIdx.x * 128 + t;
    const int p1 = p0 + 64;
    const int b = p0 >> 12;
    const float* xbase = x + (size_t)b * DDIM * HW;

    // prefetch tile 0
    {
        unsigned sq = smem_u32(&sQ[0][0]);
        unsigned ss = smem_u32(&sS[0][0]);
#pragma unroll
        for (int r = t; r < TILE; r += 64) {
            const char* src = (const char*)(g_qe + r * 16);
#pragma unroll
            for (int k = 0; k < 4; k++) cpasync16(sq + r * 64 + k * 16, src + k * 16);
            cpasync8(ss + r * 8, &g_seh[r]);
        }
        cpacommit();
    }

    const float nem = __uint_as_float(g_neB);
    const float ndem = __uint_as_float(g_ndeB);

    unsigned FA[16], FB[16];
    float sfA, w2A, sfB, w2B;
    prep_pixel(xbase + (p0 & 4095), p0, FA, sfA, w2A, nem, ndem);
    prep_pixel(xbase + (p1 & 4095), p1, FB, sfB, w2B, nem, ndem);

    float tA = -1e30f, tB = -1e30f;     // running (max - w2) threshold
    int cA = 0, cB = 0;
    const unsigned long long slabA = (unsigned long long)(g_slab + (size_t)p0 * SLAB);
    const unsigned long long slabB = (unsigned long long)(g_slab + (size_t)p1 * SLAB);

#pragma unroll 1
    for (int tile = 0; tile < NTILES; tile++) {
        if (tile + 1 < NTILES) {
            int nb = (tile + 1) & 1;
            unsigned sq = smem_u32(&sQ[nb][0]);
            unsigned ss = smem_u32(&sS[nb][0]);
#pragma unroll
            for (int r = t; r < TILE; r += 64) {
                const char* src = (const char*)(g_qe + ((tile + 1) * TILE + r) * 16);
#pragma unroll
                for (int k = 0; k < 4; k++) cpasync16(sq + r * 64 + k * 16, src + k * 16);
                cpasync8(ss + r * 8, &g_seh[(tile + 1) * TILE + r]);
            }
            cpacommit();
            cpawait<1>();
        } else {
            cpawait<0>();
        }
        __syncthreads();

        const int buf = tile & 1;
        const int jb = tile * TILE;
#pragma unroll 2
        for (int c = 0; c < TILE; c++) {
            const int4* qq = (const int4*)&sQ[buf][c * 16];
            float2 sh = sS[buf][c];
            int a0 = 0, a1 = 0, a2 = 0, a3 = 0;
            int e0 = 0, e1 = 0, e2 = 0, e3 = 0;
#pragma unroll
            for (int k = 0; k < 4; k++) {
                int4 u = qq[k];
                a0 = __dp4a(u.x, (int)FA[4 * k + 0], a0);
                a1 = __dp4a(u.y, (int)FA[4 * k + 1], a1);
                a2 = __dp4a(u.z, (int)FA[4 * k + 2], a2);
                a3 = __dp4a(u.w, (int)FA[4 * k + 3], a3);
                e0 = __dp4a(u.x, (int)FB[4 * k + 0], e0);
                e1 = __dp4a(u.y, (int)FB[4 * k + 1], e1);
                e2 = __dp4a(u.z, (int)FB[4 * k + 2], e2);
                e3 = __dp4a(u.w, (int)FB[4 * k + 3], e3);
            }
            int accA = (a0 + a1) + (a2 + a3);
            int accB = (e0 + e1) + (e2 + e3);
            float vA = fmaf((float)accA, sfA * sh.x, -sh.y);
            float vB = fmaf((float)accB, sfB * sh.x, -sh.y);
            unsigned jbits = (unsigned)(jb + c);
            emit(vA, tA, cA, slabA, jbits);
            tA = fmaxf(tA, vA - w2A);
            emit(vB, tB, cB, slabB, jbits);
            tB = fmaxf(tB, vB - w2B);
        }
        __syncthreads();
    }

    g_T[p0] = tA;
    g_T[p1] = tB;
    g_cntP[p0] = cA;
    g_cntP[p1] = cB;
}

// ---------------------------------------------------------------------------
// resolve: warp per pixel. Exact fp32 rescore of surviving candidates
// (or full scan on slab overflow). Lowest-index tie-break.
// ---------------------------------------------------------------------------
__global__ void __launch_bounds__(256) resolve() {
    const int lane = threadIdx.x & 31;
    const int p = (blockIdx.x * blockDim.x + threadIdx.x) >> 5;

    const int cnt = g_cntP[p];
    const float T = g_T[p];
    const float2 fv = ((const float2*)(g_fc + (size_t)p * DDIM))[lane];

    float bests = -3e38f;
    int bestj = 0;

    if (cnt <= SLAB) {
        float2 ent = (lane < cnt) ? g_slab[(size_t)p * SLAB + lane]
                                  : make_float2(-3e38f, 0.f);
        unsigned mask = __ballot_sync(0xFFFFFFFFu, ent.x >= T);
        while (mask) {
            int src = __ffs(mask) - 1;
            mask &= mask - 1;
            int j = __shfl_sync(0xFFFFFFFFu, __float_as_int(ent.y), src);
            float2 cv = ((const float2*)(g_codeT + (size_t)j * DDIM))[lane];
            float s = fmaf(fv.x, cv.x, fv.y * cv.y);
#pragma unroll
            for (int o = 16; o; o >>= 1) s += __shfl_xor_sync(0xFFFFFFFFu, s, o);
            s -= g_hn[j];
            if (s > bests) { bests = s; bestj = j; }   // increasing j -> lowest idx on tie
        }
    } else {
        // rare overflow: exact scan of all codes
        for (int j = 0; j < NE; j++) {
            float2 cv = ((const float2*)(g_codeT + (size_t)j * DDIM))[lane];
            float s = fmaf(fv.x, cv.x, fv.y * cv.y);
#pragma unroll
            for (int o = 16; o; o >>= 1) s += __shfl_xor_sync(0xFFFFFFFFu, s, o);
            s -= g_hn[j];
            if (s > bests) { bests = s; bestj = j; }
        }
    }
    if (lane == 0) g_widx[p] = bestj;
}

// ---------------------------------------------------------------------------
// final_gather: write quantized output + loss partials
// ---------------------------------------------------------------------------
__global__ void __launch_bounds__(256) final_gather(const float* __restrict__ x,
                                                    float* __restrict__ out) {
    __shared__ float sRed[8];
    const int t = threadIdx.x;
    const int p = blockIdx.x * 256 + t;
    const int b = p >> 12, hw = p & 4095;
    const int idx = g_widx[p];

    const float* xb = x + (size_t)b * DDIM * HW + hw;
    float* ob = out + (size_t)b * DDIM * HW + hw;
    const float4* cr = (const float4*)(g_codeT + (size_t)idx * DDIM);
    float loss = 0.f;
#pragma unroll
    for (int kk = 0; kk < 16; kk++) {
        float4 q = cr[kk];
        int d = 4 * kk;
        float r;
        ob[(d + 0) * HW] = q.x; r = q.x - xb[(d + 0) * HW]; loss += r * r;
        ob[(d + 1) * HW] = q.y; r = q.y - xb[(d + 1) * HW]; loss += r * r;
        ob[(d + 2) * HW] = q.z; r = q.z - xb[(d + 2) * HW]; loss += r * r;
        ob[(d + 3) * HW] = q.w; r = q.w - xb[(d + 3) * HW]; loss += r * r;
    }
#pragma unroll
    for (int o = 16; o; o >>= 1) loss += __shfl_xor_sync(0xFFFFFFFFu, loss, o);
    if ((t & 31) == 0) sRed[t >> 5] = loss;
    __syncthreads();
    if (t == 0) {
        float s = 0.f;
#pragma unroll
        for (int w = 0; w < 8; w++) s += sRed[w];
        g_partial[blockIdx.x] = s;
    }
}

__global__ void fin_kernel(float* __restrict__ out, int last) {
    __shared__ float sRed[16];
    int t = threadIdx.x;  // 512
    float v = g_partial[t];
#pragma unroll
    for (int o = 16; o; o >>= 1) v += __shfl_xor_sync(0xFFFFFFFFu, v, o);
    if ((t & 31) == 0) sRed[t >> 5] = v;
    __syncthreads();
    if (t == 0) {
        double s = 0.0;
#pragma unroll
        for (int w = 0; w < 16; w++) s += (double)sRed[w];
        out[last] = (float)(s / (double)QELEMS);
    }
}

// ---------------------------------------------------------------------------
extern "C" void kernel_launch(void* const* d_in, const int* in_sizes, int n_in,
                              void* d_out, int out_size) {
    const float* x = (const float*)d_in[0];
    const float* embed = (const float*)d_in[1];
    if (n_in >= 2 && in_sizes[0] == NE * DDIM && in_sizes[1] == QELEMS) {
        const float* tmp = x; x = embed; embed = tmp;
    }
    float* out = (float*)d_out;

    packB<<<4, 256>>>(embed);
    vq_pass<<<NPIX / 128, 64>>>(x);
    resolve<<<NPIX / 8, 256>>>();
    final_gather<<<NPIX / 256, 256>>>(x, out);
    fin_kernel<<<1, 512>>>(out, out_size - 1);
}